// round 1
// baseline (speedup 1.0000x reference)
#include <cuda_runtime.h>
#include <cuda_bf16.h>
#include <cstdint>

// ---------------- problem constants ----------------
#define NS      1024          // strands
#define NV      99            // points per strand (NUM_PTS-1)
#define ROWS    (NS*NV)       // 101376
#define INCH    64
#define MH      512
#define SH      512
#define KCAT    (INCH+MH)     // 576
#define SCALE0  30.0f

// ---------------- device scratch (allocation-free) ----------------
__device__ float g_wmod0[MH*INCH];
__device__ float g_wmod1[MH*KCAT];
__device__ float g_wmod2[MH*KCAT];
__device__ float g_ws1[SH*SH];
__device__ float g_ws2[SH*SH];
__device__ float g_wdec[3*SH];
__device__ float g_s0[NV*SH];          // sin(30*(t*w0+b0)) per (point, unit)
__device__ float g_M0[NS*MH];
__device__ float g_M1[NS*MH];
__device__ float g_M2[NS*MH];
__device__ float g_Z[NS*KCAT];
__device__ float g_HA[(size_t)ROWS*SH];
__device__ float g_HB[(size_t)ROWS*SH];
__device__ float g_dir[(size_t)ROWS*3];

// ---------------- weight-norm: w = g * v / ||v||_row ----------------
__global__ void rownorm_kernel(const float* __restrict__ v, const float* __restrict__ g,
                               float* __restrict__ out, int cols)
{
    int r = blockIdx.x;
    const float* vr = v + (size_t)r * cols;
    float ss = 0.f;
    for (int c = threadIdx.x; c < cols; c += blockDim.x) { float x = vr[c]; ss += x * x; }
    __shared__ float red[256];
    red[threadIdx.x] = ss; __syncthreads();
    for (int s = 128; s > 0; s >>= 1) {
        if (threadIdx.x < s) red[threadIdx.x] += red[threadIdx.x + s];
        __syncthreads();
    }
    float scale = g[r] * rsqrtf(red[0]);
    for (int c = threadIdx.x; c < cols; c += blockDim.x)
        out[(size_t)r * cols + c] = vr[c] * scale;
}

// ---------------- siren layer 0 basis: s0[p][j] = sin(30*(t_p*w_j + b_j)) ----------------
__global__ void s0_kernel(const float* __restrict__ v0, const float* __restrict__ g0,
                          const float* __restrict__ b0)
{
    int p = blockIdx.x;      // 0..98
    int j = threadIdx.x;     // 0..511
    float vv = v0[j];
    float w  = g0[j] * vv * rsqrtf(vv * vv);   // g * v/|v|  (row norm of a 1-elem row)
    float t  = (float)p / (float)(100 - 1);    // linspace(0,1,100)[p]
    g_s0[p * SH + j] = sinf(SCALE0 * (t * w + b0[j]));
}

// ---------------- concat z = [strand_features, M] ----------------
__global__ void zcat_kernel(const float* __restrict__ X, const float* __restrict__ Msrc)
{
    int s = blockIdx.x;      // strand
    int c = threadIdx.x;     // 0..575
    g_Z[(size_t)s * KCAT + c] = (c < INCH) ? X[(size_t)s * INCH + c]
                                           : Msrc[(size_t)s * MH + (c - INCH)];
}

// ---------------- H0 = (1 - M0[strand]) * s0[point] ----------------
__global__ void gate0_kernel()
{
    int r = blockIdx.x;      // row 0..ROWS-1
    int c = threadIdx.x;     // 0..511
    int s = r / NV, p = r - s * NV;
    g_HA[(size_t)r * SH + c] = (1.f - g_M0[(size_t)s * MH + c]) * g_s0[p * SH + c];
}

// ---------------- tiled GEMM + fused activation ----------------
// out[row, col] = act( sum_k A[row,k]*W[col,k] + bias[col] )
//   act==0: silu  (modulation layers)
//   act==1: (1 - gate[strand(row), col]) * sin(.)  (siren layers 1,2)
// Requires: M % 128 == 0, N == 512, K % 16 == 0, all pointers 16B-aligned.
#define BM 128
#define BN 64
#define BK 16
#define TM 8
#define TN 4
__global__ __launch_bounds__(256, 4)
void gemm_act_kernel(const float* __restrict__ A, const float* __restrict__ W,
                     const float* __restrict__ bias, const float* __restrict__ gate,
                     float* __restrict__ out, int K, int act)
{
    __shared__ float As[BK][BM + 4];
    __shared__ float Bs[BK][BN];

    const int tid = threadIdx.x;
    const int tx  = tid & 15;        // 0..15 -> N
    const int ty  = tid >> 4;        // 0..15 -> M
    const int rowBase = blockIdx.y * BM;
    const int colBase = blockIdx.x * BN;

    float acc[TM][TN] = {};

    for (int k0 = 0; k0 < K; k0 += BK) {
        // A tile: 128x16 = 512 float4, 2 per thread
        #pragma unroll
        for (int i = 0; i < 2; i++) {
            int f  = tid + i * 256;
            int r  = f >> 2;
            int c4 = f & 3;
            float4 v = *reinterpret_cast<const float4*>(
                &A[(size_t)(rowBase + r) * K + k0 + c4 * 4]);
            As[c4 * 4 + 0][r] = v.x; As[c4 * 4 + 1][r] = v.y;
            As[c4 * 4 + 2][r] = v.z; As[c4 * 4 + 3][r] = v.w;
        }
        // B tile: 64x16 = 256 float4, 1 per thread
        {
            int r  = tid >> 2;
            int c4 = tid & 3;
            float4 v = *reinterpret_cast<const float4*>(
                &W[(size_t)(colBase + r) * K + k0 + c4 * 4]);
            Bs[c4 * 4 + 0][r] = v.x; Bs[c4 * 4 + 1][r] = v.y;
            Bs[c4 * 4 + 2][r] = v.z; Bs[c4 * 4 + 3][r] = v.w;
        }
        __syncthreads();

        #pragma unroll
        for (int k = 0; k < BK; k++) {
            float a[TM], b[TN];
            float4 a0 = *reinterpret_cast<const float4*>(&As[k][ty * TM + 0]);
            float4 a1 = *reinterpret_cast<const float4*>(&As[k][ty * TM + 4]);
            a[0]=a0.x; a[1]=a0.y; a[2]=a0.z; a[3]=a0.w;
            a[4]=a1.x; a[5]=a1.y; a[6]=a1.z; a[7]=a1.w;
            float4 b0 = *reinterpret_cast<const float4*>(&Bs[k][tx * TN]);
            b[0]=b0.x; b[1]=b0.y; b[2]=b0.z; b[3]=b0.w;
            #pragma unroll
            for (int i = 0; i < TM; i++)
                #pragma unroll
                for (int j = 0; j < TN; j++)
                    acc[i][j] = fmaf(a[i], b[j], acc[i][j]);
        }
        __syncthreads();
    }

    // epilogue
    #pragma unroll
    for (int i = 0; i < TM; i++) {
        int row = rowBase + ty * TM + i;
        int strand = row / NV;
        #pragma unroll
        for (int j = 0; j < TN; j++) {
            int col = colBase + tx * TN + j;
            float v = acc[i][j] + bias[col];
            if (act == 0) {
                v = v / (1.f + expf(-v));                 // silu
            } else {
                float s = sinf(v);
                v = (1.f - gate[(size_t)strand * MH + col]) * s;
            }
            out[(size_t)row * 512 + col] = v;
        }
    }
}

// ---------------- decoder: dir[row] = 0.01*(H2[row] @ Wdec^T + bdec) ----------------
__global__ void dec_kernel(const float* __restrict__ H, const float* __restrict__ bd)
{
    __shared__ float wd[3 * SH];
    for (int i = threadIdx.x; i < 3 * SH; i += blockDim.x) wd[i] = g_wdec[i];
    __syncthreads();

    int warp = threadIdx.x >> 5;
    int lane = threadIdx.x & 31;
    size_t row = (size_t)blockIdx.x * 8 + warp;
    const float* h = H + row * SH;
    float a0 = 0.f, a1 = 0.f, a2 = 0.f;
    for (int i = lane; i < SH; i += 32) {
        float x = h[i];
        a0 = fmaf(x, wd[i],          a0);
        a1 = fmaf(x, wd[SH + i],     a1);
        a2 = fmaf(x, wd[2 * SH + i], a2);
    }
    #pragma unroll
    for (int o = 16; o > 0; o >>= 1) {
        a0 += __shfl_down_sync(0xFFFFFFFFu, a0, o);
        a1 += __shfl_down_sync(0xFFFFFFFFu, a1, o);
        a2 += __shfl_down_sync(0xFFFFFFFFu, a2, o);
    }
    if (lane == 0) {
        g_dir[row * 3 + 0] = (a0 + bd[0]) * 0.01f;
        g_dir[row * 3 + 1] = (a1 + bd[1]) * 0.01f;
        g_dir[row * 3 + 2] = (a2 + bd[2]) * 0.01f;
    }
}

// ---------------- cumsum over points + leading zero ----------------
__global__ void cumsum_kernel(float* __restrict__ out)
{
    int idx = blockIdx.x * blockDim.x + threadIdx.x;   // 0..3071
    if (idx >= NS * 3) return;
    int s = idx / 3, d = idx - s * 3;
    float acc = 0.f;
    out[(size_t)s * 300 + d] = 0.f;
    for (int p = 0; p < NV; p++) {
        acc += g_dir[((size_t)s * NV + p) * 3 + d];
        out[(size_t)s * 300 + (size_t)(p + 1) * 3 + d] = acc;
    }
}

// ---------------- host launch ----------------
static void* sym(const void* s) { void* p = nullptr; cudaGetSymbolAddress(&p, s); return p; }

extern "C" void kernel_launch(void* const* d_in, const int* in_sizes, int n_in,
                              void* d_out, int out_size)
{
    const float* X   = (const float*)d_in[0];
    const float* mv0 = (const float*)d_in[1];  const float* mg0 = (const float*)d_in[2];  const float* mb0 = (const float*)d_in[3];
    const float* mv1 = (const float*)d_in[4];  const float* mg1 = (const float*)d_in[5];  const float* mb1 = (const float*)d_in[6];
    const float* mv2 = (const float*)d_in[7];  const float* mg2 = (const float*)d_in[8];  const float* mb2 = (const float*)d_in[9];
    const float* sv0 = (const float*)d_in[10]; const float* sg0 = (const float*)d_in[11]; const float* sb0 = (const float*)d_in[12];
    const float* sv1 = (const float*)d_in[13]; const float* sg1 = (const float*)d_in[14]; const float* sb1 = (const float*)d_in[15];
    const float* sv2 = (const float*)d_in[16]; const float* sg2 = (const float*)d_in[17]; const float* sb2 = (const float*)d_in[18];
    const float* dv  = (const float*)d_in[19]; const float* dg  = (const float*)d_in[20]; const float* db  = (const float*)d_in[21];
    float* out = (float*)d_out;

    float* wmod0 = (float*)sym(g_wmod0);
    float* wmod1 = (float*)sym(g_wmod1);
    float* wmod2 = (float*)sym(g_wmod2);
    float* ws1   = (float*)sym(g_ws1);
    float* ws2   = (float*)sym(g_ws2);
    float* wdec  = (float*)sym(g_wdec);
    float* M0    = (float*)sym(g_M0);
    float* M1    = (float*)sym(g_M1);
    float* M2    = (float*)sym(g_M2);
    float* Z     = (float*)sym(g_Z);
    float* HA    = (float*)sym(g_HA);
    float* HB    = (float*)sym(g_HB);

    // 1. weight-norm all matrices
    rownorm_kernel<<<MH, 256>>>(mv0, mg0, wmod0, INCH);
    rownorm_kernel<<<MH, 256>>>(mv1, mg1, wmod1, KCAT);
    rownorm_kernel<<<MH, 256>>>(mv2, mg2, wmod2, KCAT);
    rownorm_kernel<<<SH, 256>>>(sv1, sg1, ws1, SH);
    rownorm_kernel<<<SH, 256>>>(sv2, sg2, ws2, SH);
    rownorm_kernel<<<3,  256>>>(dv,  dg,  wdec, SH);

    // 2. siren-0 basis table (99 x 512)
    s0_kernel<<<NV, SH>>>(sv0, sg0, sb0);

    // 3. modulation chain (per-strand only: 1024 rows)
    {
        dim3 grid(512 / BN, NS / BM);
        gemm_act_kernel<<<grid, 256>>>(X, wmod0, mb0, nullptr, M0, INCH, 0);
        zcat_kernel<<<NS, KCAT>>>(X, M0);
        gemm_act_kernel<<<grid, 256>>>(Z, wmod1, mb1, nullptr, M1, KCAT, 0);
        zcat_kernel<<<NS, KCAT>>>(X, M1);
        gemm_act_kernel<<<grid, 256>>>(Z, wmod2, mb2, nullptr, M2, KCAT, 0);
    }

    // 4. H0 = (1 - M0) * s0
    gate0_kernel<<<ROWS, SH>>>();

    // 5. two big fused siren GEMMs (101376 x 512 x 512)
    {
        dim3 grid(512 / BN, ROWS / BM);
        gemm_act_kernel<<<grid, 256>>>(HA, ws1, sb1, M1, HB, SH, 1);
        gemm_act_kernel<<<grid, 256>>>(HB, ws2, sb2, M2, HA, SH, 1);
    }

    // 6. decoder + cumsum
    dec_kernel<<<ROWS / 8, 256>>>(HA, db);
    cumsum_kernel<<<(NS * 3 + 255) / 256, 256>>>(out);
    (void)in_sizes; (void)n_in; (void)out_size;
}

// round 2
// speedup vs baseline: 2.7309x; 2.7309x over previous
#include <cuda_runtime.h>
#include <cuda_bf16.h>
#include <cstdint>

// ---------------- problem constants ----------------
#define NS      1024
#define NV      99
#define ROWS    (NS*NV)       // 101376
#define INCH    64
#define MH      512
#define SH      512
#define KCAT    (INCH+MH)     // 576
#define SCALE0  30.0f

// ---------------- device scratch ----------------
__device__ float g_wmod0[MH*INCH];
__device__ float g_wmod1[MH*KCAT];
__device__ float g_wmod2[MH*KCAT];
__device__ float g_ws1[SH*SH];
__device__ float g_ws2[SH*SH];
__device__ float g_wdec[3*SH];
__device__ float g_s0[NV*SH];
__device__ float g_M0[NS*MH];
__device__ float g_M1[NS*MH];
__device__ float g_M2[NS*MH];
__device__ float g_Z[NS*KCAT];
__device__ float g_Xr[NS*INCH];
__device__ float g_HA[(size_t)ROWS*SH];
__device__ float g_HB[(size_t)ROWS*SH];
__device__ float g_dir[(size_t)ROWS*3];

__device__ __forceinline__ float rna_tf32(float x){
    float y; asm("cvt.rna.tf32.f32 %0, %1;" : "=f"(y) : "f"(x)); return y;
}

// ---------------- weight-norm: w = g * v / ||v||_row (optionally tf32-rounded) ----
__global__ void rownorm_kernel(const float* __restrict__ v, const float* __restrict__ g,
                               float* __restrict__ out, int cols, int rnd)
{
    int r = blockIdx.x;
    const float* vr = v + (size_t)r * cols;
    float ss = 0.f;
    for (int c = threadIdx.x; c < cols; c += blockDim.x) { float x = vr[c]; ss += x * x; }
    __shared__ float red[256];
    red[threadIdx.x] = ss; __syncthreads();
    for (int s = 128; s > 0; s >>= 1) {
        if (threadIdx.x < s) red[threadIdx.x] += red[threadIdx.x + s];
        __syncthreads();
    }
    float scale = g[r] * rsqrtf(red[0]);
    for (int c = threadIdx.x; c < cols; c += blockDim.x) {
        float w = vr[c] * scale;
        out[(size_t)r * cols + c] = rnd ? rna_tf32(w) : w;
    }
}

// ---------------- siren-0 basis: s0[p][j] = sin(30*(t_p*w_j + b_j)) ----------------
__global__ void s0_kernel(const float* __restrict__ v0, const float* __restrict__ g0,
                          const float* __restrict__ b0)
{
    int p = blockIdx.x, j = threadIdx.x;
    float vv = v0[j];
    float w  = g0[j] * vv * rsqrtf(vv * vv);
    float t  = (float)p / (float)(100 - 1);
    g_s0[p * SH + j] = sinf(SCALE0 * (t * w + b0[j]));
}

// ---------------- round X to tf32 ----------------
__global__ void roundX_kernel(const float* __restrict__ X)
{
    int i = blockIdx.x * blockDim.x + threadIdx.x;
    if (i < NS * INCH) g_Xr[i] = rna_tf32(X[i]);
}

// ---------------- z = [rna(X), rna(M)] ----------------
__global__ void zcat_kernel(const float* __restrict__ X, const float* __restrict__ Msrc)
{
    int s = blockIdx.x, c = threadIdx.x;
    float v = (c < INCH) ? X[(size_t)s * INCH + c] : Msrc[(size_t)s * MH + (c - INCH)];
    g_Z[(size_t)s * KCAT + c] = rna_tf32(v);
}

// ---------------- H0 = rna((1 - M0[strand]) * s0[point]) ----------------
__global__ void gate0_kernel()
{
    int r = blockIdx.x, c = threadIdx.x;
    int s = r / NV, p = r - s * NV;
    g_HA[(size_t)r * SH + c] =
        rna_tf32((1.f - g_M0[(size_t)s * MH + c]) * g_s0[p * SH + c]);
}

// ---------------- tf32 tensor-core GEMM + fused activation ----------------
// out[row, col] = act( sum_k A[row,k]*W[col,k] + bias[col] ), N fixed at 512 output stride
//   act==0: silu                      (modulation layers)
//   act==1: (1-gate)*sin, tf32 store  (siren layer 1 -> feeds next MMA)
//   act==2: (1-gate)*sin, fp32 store  (siren layer 2 -> feeds decoder)
#define BM 128
#define BN 128
#define BK 32
#define SST 36   // smem row stride (floats): banks = (4g+t) mod 32, conflict-free frags

__device__ __forceinline__ void cp16(uint32_t s, const void* g){
    asm volatile("cp.async.cg.shared.global [%0], [%1], 16;" :: "r"(s), "l"(g));
}

__global__ __launch_bounds__(256, 2)
void gemm_tf32_kernel(const float* __restrict__ A, const float* __restrict__ W,
                      const float* __restrict__ bias, const float* __restrict__ gate,
                      float* __restrict__ out, int K, int act)
{
    extern __shared__ float sm[];
    float* sA = sm;                      // 2 * BM * SST
    float* sB = sm + 2 * BM * SST;       // 2 * BN * SST

    const int tid = threadIdx.x;
    const int rowBase = blockIdx.y * BM;
    const int colBase = blockIdx.x * BN;
    const uint32_t sA_u = (uint32_t)__cvta_generic_to_shared(sA);
    const uint32_t sB_u = (uint32_t)__cvta_generic_to_shared(sB);

    const int lane = tid & 31, warp = tid >> 5;
    const int wm = warp & 3, wn = warp >> 2;   // 4x2 warp grid -> 32x64 warp tile
    const int gg = lane >> 2, tt = lane & 3;

    float acc[2][8][4] = {};
    const int nk = K / BK;

    auto load_stage = [&](int i, int buf){
        int k0 = i * BK;
        #pragma unroll
        for (int it = 0; it < 4; it++){
            int c  = tid + it * 256;
            int r  = c >> 3;
            int kc = (c & 7) * 4;
            cp16(sA_u + (uint32_t)((buf * BM * SST + r * SST + kc) * 4),
                 &A[(size_t)(rowBase + r) * K + k0 + kc]);
            cp16(sB_u + (uint32_t)((buf * BN * SST + r * SST + kc) * 4),
                 &W[(size_t)(colBase + r) * K + k0 + kc]);
        }
        asm volatile("cp.async.commit_group;");
    };

    load_stage(0, 0);
    for (int i = 0; i < nk; i++){
        if (i + 1 < nk) {
            load_stage(i + 1, (i + 1) & 1);
            asm volatile("cp.async.wait_group 1;");
        } else {
            asm volatile("cp.async.wait_group 0;");
        }
        __syncthreads();
        const float* cA = sA + (i & 1) * BM * SST;
        const float* cB = sB + (i & 1) * BN * SST;
        #pragma unroll
        for (int kk = 0; kk < BK; kk += 8){
            uint32_t a[2][4], b[8][2];
            #pragma unroll
            for (int mi = 0; mi < 2; mi++){
                int r = wm * 32 + mi * 16 + gg;
                a[mi][0] = __float_as_uint(cA[r * SST + kk + tt]);
                a[mi][1] = __float_as_uint(cA[(r + 8) * SST + kk + tt]);
                a[mi][2] = __float_as_uint(cA[r * SST + kk + tt + 4]);
                a[mi][3] = __float_as_uint(cA[(r + 8) * SST + kk + tt + 4]);
            }
            #pragma unroll
            for (int ni = 0; ni < 8; ni++){
                int c = wn * 64 + ni * 8 + gg;
                b[ni][0] = __float_as_uint(cB[c * SST + kk + tt]);
                b[ni][1] = __float_as_uint(cB[c * SST + kk + tt + 4]);
            }
            #pragma unroll
            for (int mi = 0; mi < 2; mi++)
                #pragma unroll
                for (int ni = 0; ni < 8; ni++){
                    float* d = acc[mi][ni];
                    asm volatile(
                        "mma.sync.aligned.m16n8k8.row.col.f32.tf32.tf32.f32 "
                        "{%0,%1,%2,%3}, {%4,%5,%6,%7}, {%8,%9}, {%0,%1,%2,%3};"
                        : "+f"(d[0]), "+f"(d[1]), "+f"(d[2]), "+f"(d[3])
                        : "r"(a[mi][0]), "r"(a[mi][1]), "r"(a[mi][2]), "r"(a[mi][3]),
                          "r"(b[ni][0]), "r"(b[ni][1]));
                }
        }
        __syncthreads();
    }

    // ---- epilogue ----
    #pragma unroll
    for (int mi = 0; mi < 2; mi++){
        int row0 = rowBase + wm * 32 + mi * 16 + gg;
        int row1 = row0 + 8;
        int s0i = row0 / NV, s1i = row1 / NV;
        #pragma unroll
        for (int ni = 0; ni < 8; ni++){
            int col = colBase + wn * 64 + ni * 8 + tt * 2;
            float b0 = bias[col], b1 = bias[col + 1];
            float v00 = acc[mi][ni][0] + b0, v01 = acc[mi][ni][1] + b1;
            float v10 = acc[mi][ni][2] + b0, v11 = acc[mi][ni][3] + b1;
            if (act == 0){
                v00 = v00 / (1.f + __expf(-v00));
                v01 = v01 / (1.f + __expf(-v01));
                v10 = v10 / (1.f + __expf(-v10));
                v11 = v11 / (1.f + __expf(-v11));
            } else {
                float g00 = 1.f - gate[(size_t)s0i * MH + col];
                float g01 = 1.f - gate[(size_t)s0i * MH + col + 1];
                float g10 = 1.f - gate[(size_t)s1i * MH + col];
                float g11 = 1.f - gate[(size_t)s1i * MH + col + 1];
                v00 = g00 * __sinf(v00); v01 = g01 * __sinf(v01);
                v10 = g10 * __sinf(v10); v11 = g11 * __sinf(v11);
                if (act == 1){
                    v00 = rna_tf32(v00); v01 = rna_tf32(v01);
                    v10 = rna_tf32(v10); v11 = rna_tf32(v11);
                }
            }
            *reinterpret_cast<float2*>(&out[(size_t)row0 * 512 + col]) = make_float2(v00, v01);
            *reinterpret_cast<float2*>(&out[(size_t)row1 * 512 + col]) = make_float2(v10, v11);
        }
    }
}

// ---------------- decoder ----------------
__global__ void dec_kernel(const float* __restrict__ H, const float* __restrict__ bd)
{
    __shared__ float wd[3 * SH];
    for (int i = threadIdx.x; i < 3 * SH; i += blockDim.x) wd[i] = g_wdec[i];
    __syncthreads();
    int warp = threadIdx.x >> 5, lane = threadIdx.x & 31;
    size_t row = (size_t)blockIdx.x * 8 + warp;
    const float* h = H + row * SH;
    float a0 = 0.f, a1 = 0.f, a2 = 0.f;
    for (int i = lane; i < SH; i += 32) {
        float x = h[i];
        a0 = fmaf(x, wd[i], a0);
        a1 = fmaf(x, wd[SH + i], a1);
        a2 = fmaf(x, wd[2 * SH + i], a2);
    }
    #pragma unroll
    for (int o = 16; o > 0; o >>= 1) {
        a0 += __shfl_down_sync(0xFFFFFFFFu, a0, o);
        a1 += __shfl_down_sync(0xFFFFFFFFu, a1, o);
        a2 += __shfl_down_sync(0xFFFFFFFFu, a2, o);
    }
    if (lane == 0) {
        g_dir[row * 3 + 0] = (a0 + bd[0]) * 0.01f;
        g_dir[row * 3 + 1] = (a1 + bd[1]) * 0.01f;
        g_dir[row * 3 + 2] = (a2 + bd[2]) * 0.01f;
    }
}

// ---------------- cumsum ----------------
__global__ void cumsum_kernel(float* __restrict__ out)
{
    int idx = blockIdx.x * blockDim.x + threadIdx.x;
    if (idx >= NS * 3) return;
    int s = idx / 3, d = idx - s * 3;
    float acc = 0.f;
    out[(size_t)s * 300 + d] = 0.f;
    for (int p = 0; p < NV; p++) {
        acc += g_dir[((size_t)s * NV + p) * 3 + d];
        out[(size_t)s * 300 + (size_t)(p + 1) * 3 + d] = acc;
    }
}

// ---------------- host launch ----------------
static void* sym(const void* s) { void* p = nullptr; cudaGetSymbolAddress(&p, s); return p; }

extern "C" void kernel_launch(void* const* d_in, const int* in_sizes, int n_in,
                              void* d_out, int out_size)
{
    const float* X   = (const float*)d_in[0];
    const float* mv0 = (const float*)d_in[1];  const float* mg0 = (const float*)d_in[2];  const float* mb0 = (const float*)d_in[3];
    const float* mv1 = (const float*)d_in[4];  const float* mg1 = (const float*)d_in[5];  const float* mb1 = (const float*)d_in[6];
    const float* mv2 = (const float*)d_in[7];  const float* mg2 = (const float*)d_in[8];  const float* mb2 = (const float*)d_in[9];
    const float* sv0 = (const float*)d_in[10]; const float* sg0 = (const float*)d_in[11]; const float* sb0 = (const float*)d_in[12];
    const float* sv1 = (const float*)d_in[13]; const float* sg1 = (const float*)d_in[14]; const float* sb1 = (const float*)d_in[15];
    const float* sv2 = (const float*)d_in[16]; const float* sg2 = (const float*)d_in[17]; const float* sb2 = (const float*)d_in[18];
    const float* dv  = (const float*)d_in[19]; const float* dg  = (const float*)d_in[20]; const float* db  = (const float*)d_in[21];
    float* out = (float*)d_out;

    float* wmod0 = (float*)sym(g_wmod0);
    float* wmod1 = (float*)sym(g_wmod1);
    float* wmod2 = (float*)sym(g_wmod2);
    float* ws1   = (float*)sym(g_ws1);
    float* ws2   = (float*)sym(g_ws2);
    float* wdec  = (float*)sym(g_wdec);
    float* M0    = (float*)sym(g_M0);
    float* M1    = (float*)sym(g_M1);
    float* M2    = (float*)sym(g_M2);
    float* Z     = (float*)sym(g_Z);
    float* Xr    = (float*)sym(g_Xr);
    float* HA    = (float*)sym(g_HA);
    float* HB    = (float*)sym(g_HB);

    const int smem_bytes = 2 * (BM + BN) * SST * 4;   // 73728
    static int attr_done = 0;
    if (!attr_done) {
        cudaFuncSetAttribute(gemm_tf32_kernel,
                             cudaFuncAttributeMaxDynamicSharedMemorySize, smem_bytes);
        attr_done = 1;
    }

    // 1. weight-norm (tf32-rounded where used as MMA operand)
    rownorm_kernel<<<MH, 256>>>(mv0, mg0, wmod0, INCH, 1);
    rownorm_kernel<<<MH, 256>>>(mv1, mg1, wmod1, KCAT, 1);
    rownorm_kernel<<<MH, 256>>>(mv2, mg2, wmod2, KCAT, 1);
    rownorm_kernel<<<SH, 256>>>(sv1, sg1, ws1, SH, 1);
    rownorm_kernel<<<SH, 256>>>(sv2, sg2, ws2, SH, 1);
    rownorm_kernel<<<3,  256>>>(dv,  dg,  wdec, SH, 0);

    // 2. siren-0 basis + rounded X
    s0_kernel<<<NV, SH>>>(sv0, sg0, sb0);
    roundX_kernel<<<(NS * INCH + 255) / 256, 256>>>(X);

    // 3. modulation chain
    {
        dim3 grid(512 / BN, NS / BM);
        gemm_tf32_kernel<<<grid, 256, smem_bytes>>>(Xr, wmod0, mb0, nullptr, M0, INCH, 0);
        zcat_kernel<<<NS, KCAT>>>(X, M0);
        gemm_tf32_kernel<<<grid, 256, smem_bytes>>>(Z, wmod1, mb1, nullptr, M1, KCAT, 0);
        zcat_kernel<<<NS, KCAT>>>(X, M1);
        gemm_tf32_kernel<<<grid, 256, smem_bytes>>>(Z, wmod2, mb2, nullptr, M2, KCAT, 0);
    }

    // 4. H0 = rna((1-M0)*s0)
    gate0_kernel<<<ROWS, SH>>>();

    // 5. two big tensor-core GEMMs
    {
        dim3 grid(512 / BN, ROWS / BM);
        gemm_tf32_kernel<<<grid, 256, smem_bytes>>>(HA, ws1, sb1, M1, HB, SH, 1);
        gemm_tf32_kernel<<<grid, 256, smem_bytes>>>(HB, ws2, sb2, M2, HA, SH, 2);
    }

    // 6. decoder + cumsum
    dec_kernel<<<ROWS / 8, 256>>>(HA, db);
    cumsum_kernel<<<(NS * 3 + 255) / 256, 256>>>(out);
    (void)in_sizes; (void)n_in; (void)out_size;
}

// round 6
// speedup vs baseline: 3.2532x; 1.1913x over previous
#include <cuda_runtime.h>
#include <cuda_fp16.h>
#include <cstdint>

// ---------------- problem constants ----------------
#define NS      1024
#define NV      99
#define ROWS    (NS*NV)       // 101376
#define INCH    64
#define MH      512
#define SH      512
#define KCAT    (INCH+MH)     // 576
#define SCALE0  30.0f

// ---------------- device scratch ----------------
__device__ float  g_wmod0[MH*INCH];
__device__ float  g_wmod1[MH*KCAT];
__device__ float  g_wmod2[MH*KCAT];
__device__ __half g_hW1[SH*SH];
__device__ __half g_hW2[SH*SH];
__device__ float  g_wdec[3*SH];
__device__ float  g_s0[NV*SH];
__device__ float  g_M0[NS*MH];
__device__ float  g_M1[NS*MH];
__device__ float  g_M2[NS*MH];
__device__ float  g_Z0[NS*KCAT];
__device__ float  g_Z1[NS*KCAT];
__device__ float  g_Xr[NS*INCH];
__device__ __half g_hHA[(size_t)ROWS*SH];
__device__ __half g_hHB[(size_t)ROWS*SH];
__device__ float  g_dir[(size_t)ROWS*3];

__device__ __forceinline__ float rna_tf32(float x){
    float y; asm("cvt.rna.tf32.f32 %0, %1;" : "=f"(y) : "f"(x)); return y;
}
__device__ __forceinline__ void cp16(uint32_t s, const void* g){
    asm volatile("cp.async.cg.shared.global [%0], [%1], 16;" :: "r"(s), "l"(g));
}

// ================= prep: weight-norms + s0 + X rounding (one launch) ============
__global__ void prep_kernel(const float* __restrict__ mv0, const float* __restrict__ mg0,
                            const float* __restrict__ mv1, const float* __restrict__ mg1,
                            const float* __restrict__ mv2, const float* __restrict__ mg2,
                            const float* __restrict__ sv1, const float* __restrict__ sg1,
                            const float* __restrict__ sv2, const float* __restrict__ sg2,
                            const float* __restrict__ dv,  const float* __restrict__ dg,
                            const float* __restrict__ sv0, const float* __restrict__ sg0,
                            const float* __restrict__ sb0, const float* __restrict__ X)
{
    __shared__ float red[256];
    int b = blockIdx.x, tid = threadIdx.x;
    if (b < 2563) {
        const float* v; const float* g; int cols, r, mode; // 0=fp32,1=tf32,2=half
        float*  o32 = nullptr; __half* o16 = nullptr;
        if      (b < 512)  { v=mv0; g=mg0; o32=g_wmod0; cols=INCH; r=b;      mode=1; }
        else if (b < 1024) { v=mv1; g=mg1; o32=g_wmod1; cols=KCAT; r=b-512;  mode=1; }
        else if (b < 1536) { v=mv2; g=mg2; o32=g_wmod2; cols=KCAT; r=b-1024; mode=1; }
        else if (b < 2048) { v=sv1; g=sg1; o16=g_hW1;   cols=SH;   r=b-1536; mode=2; }
        else if (b < 2560) { v=sv2; g=sg2; o16=g_hW2;   cols=SH;   r=b-2048; mode=2; }
        else               { v=dv;  g=dg;  o32=g_wdec;  cols=SH;   r=b-2560; mode=0; }
        const float* vr = v + (size_t)r * cols;
        float ss = 0.f;
        for (int c = tid; c < cols; c += 256) { float x = vr[c]; ss += x * x; }
        red[tid] = ss; __syncthreads();
        for (int s = 128; s > 0; s >>= 1) {
            if (tid < s) red[tid] += red[tid + s];
            __syncthreads();
        }
        float scale = g[r] * rsqrtf(red[0]);
        for (int c = tid; c < cols; c += 256) {
            float w = vr[c] * scale;
            if (mode == 2)      o16[(size_t)r * cols + c] = __float2half(w);
            else if (mode == 1) o32[(size_t)r * cols + c] = rna_tf32(w);
            else                o32[(size_t)r * cols + c] = w;
        }
    } else if (b < 2662) {          // s0 table
        int p = b - 2563;
        float t = (float)p / 99.f;
        for (int j = tid; j < SH; j += 256) {
            float vv = sv0[j];
            float w  = sg0[j] * vv * rsqrtf(vv * vv);
            g_s0[p * SH + j] = sinf(SCALE0 * (t * w + sb0[j]));
        }
    } else {                        // X rounding + Z prefix
        int i0 = (b - 2662) * 256 + tid;
        for (int i = i0; i < NS * INCH; i += 64 * 256) {
            float v = rna_tf32(X[i]);
            int s = i >> 6, c = i & 63;
            g_Xr[i] = v;
            g_Z0[(size_t)s * KCAT + c] = v;
            g_Z1[(size_t)s * KCAT + c] = v;
        }
    }
}

// ================= mod GEMM (mma.sync tf32, silu, Z-writeback) ==========
#define BMM 128
#define BNM 128
#define BKM 32
#define SST 36
__global__ __launch_bounds__(256, 2)
void gemm_mod_kernel(const float* __restrict__ A, const float* __restrict__ W,
                     const float* __restrict__ bias, float* __restrict__ out,
                     float* __restrict__ zout, int K)
{
    extern __shared__ float sm[];
    float* sA = sm;
    float* sB = sm + 2 * BMM * SST;
    const int tid = threadIdx.x;
    const int rowBase = blockIdx.y * BMM;
    const int colBase = blockIdx.x * BNM;
    const uint32_t sA_u = (uint32_t)__cvta_generic_to_shared(sA);
    const uint32_t sB_u = (uint32_t)__cvta_generic_to_shared(sB);
    const int lane = tid & 31, warp = tid >> 5;
    const int wm = warp & 3, wn = warp >> 2;
    const int gg = lane >> 2, tt = lane & 3;
    float acc[2][8][4] = {};
    const int nk = K / BKM;

    auto load_stage = [&](int i, int buf){
        int k0 = i * BKM;
        #pragma unroll
        for (int it = 0; it < 4; it++){
            int c  = tid + it * 256;
            int r  = c >> 3;
            int kc = (c & 7) * 4;
            cp16(sA_u + (uint32_t)((buf * BMM * SST + r * SST + kc) * 4),
                 &A[(size_t)(rowBase + r) * K + k0 + kc]);
            cp16(sB_u + (uint32_t)((buf * BNM * SST + r * SST + kc) * 4),
                 &W[(size_t)(colBase + r) * K + k0 + kc]);
        }
        asm volatile("cp.async.commit_group;");
    };

    load_stage(0, 0);
    for (int i = 0; i < nk; i++){
        if (i + 1 < nk) { load_stage(i + 1, (i + 1) & 1); asm volatile("cp.async.wait_group 1;"); }
        else            { asm volatile("cp.async.wait_group 0;"); }
        __syncthreads();
        const float* cA = sA + (i & 1) * BMM * SST;
        const float* cB = sB + (i & 1) * BNM * SST;
        #pragma unroll
        for (int kk = 0; kk < BKM; kk += 8){
            uint32_t a[2][4], b[8][2];
            #pragma unroll
            for (int mi = 0; mi < 2; mi++){
                int r = wm * 32 + mi * 16 + gg;
                a[mi][0] = __float_as_uint(cA[r * SST + kk + tt]);
                a[mi][1] = __float_as_uint(cA[(r + 8) * SST + kk + tt]);
                a[mi][2] = __float_as_uint(cA[r * SST + kk + tt + 4]);
                a[mi][3] = __float_as_uint(cA[(r + 8) * SST + kk + tt + 4]);
            }
            #pragma unroll
            for (int ni = 0; ni < 8; ni++){
                int c = wn * 64 + ni * 8 + gg;
                b[ni][0] = __float_as_uint(cB[c * SST + kk + tt]);
                b[ni][1] = __float_as_uint(cB[c * SST + kk + tt + 4]);
            }
            #pragma unroll
            for (int mi = 0; mi < 2; mi++)
                #pragma unroll
                for (int ni = 0; ni < 8; ni++){
                    float* d = acc[mi][ni];
                    asm volatile(
                        "mma.sync.aligned.m16n8k8.row.col.f32.tf32.tf32.f32 "
                        "{%0,%1,%2,%3}, {%4,%5,%6,%7}, {%8,%9}, {%0,%1,%2,%3};"
                        : "+f"(d[0]), "+f"(d[1]), "+f"(d[2]), "+f"(d[3])
                        : "r"(a[mi][0]), "r"(a[mi][1]), "r"(a[mi][2]), "r"(a[mi][3]),
                          "r"(b[ni][0]), "r"(b[ni][1]));
                }
        }
        __syncthreads();
    }

    #pragma unroll
    for (int mi = 0; mi < 2; mi++){
        int row0 = rowBase + wm * 32 + mi * 16 + gg;
        #pragma unroll
        for (int ni = 0; ni < 8; ni++){
            int col = colBase + wn * 64 + ni * 8 + tt * 2;
            float b0 = bias[col], b1 = bias[col + 1];
            #pragma unroll
            for (int h = 0; h < 2; h++){
                int row = row0 + h * 8;
                float v0 = acc[mi][ni][h * 2 + 0] + b0;
                float v1 = acc[mi][ni][h * 2 + 1] + b1;
                v0 = v0 / (1.f + __expf(-v0));
                v1 = v1 / (1.f + __expf(-v1));
                *reinterpret_cast<float2*>(&out[(size_t)row * 512 + col]) = make_float2(v0, v1);
                if (zout)
                    *reinterpret_cast<float2*>(&zout[(size_t)row * KCAT + 64 + col]) =
                        make_float2(rna_tf32(v0), rna_tf32(v1));
            }
        }
    }
}

// ================= H0(half) = (1 - M0[strand]) * s0[point] ======================
__global__ void gate0_kernel()
{
    int r = blockIdx.x, c = threadIdx.x;
    int s = r / NV, p = r - s * NV;
    g_hHA[(size_t)r * SH + c] =
        __float2half((1.f - g_M0[(size_t)s * MH + c]) * g_s0[p * SH + c]);
}

// ================= fp16 tensor-core GEMM (101376 x 512 x 512) ====================
// out(half)[row,col] = (1 - gate[strand,col]) * sin( A @ W^T + bias )
#define BK2 64    // halves per k-tile (128 bytes per row)
__device__ __forceinline__ void ldsm4(uint32_t& r0, uint32_t& r1, uint32_t& r2, uint32_t& r3,
                                      uint32_t addr){
    asm volatile("ldmatrix.sync.aligned.m8n8.x4.shared.b16 {%0,%1,%2,%3}, [%4];"
                 : "=r"(r0), "=r"(r1), "=r"(r2), "=r"(r3) : "r"(addr));
}

__global__ __launch_bounds__(256, 2)
void tc_fp16_kernel(const __half* __restrict__ A, const __half* __restrict__ W,
                    const float* __restrict__ bias, const float* __restrict__ gate,
                    __half* __restrict__ out)
{
    extern __shared__ __align__(1024) char smem_raw[];
    uint32_t base  = (uint32_t)__cvta_generic_to_shared(smem_raw);
    uint32_t abase = (base + 1023u) & ~1023u;
    // stage s: A at abase + s*32768, B at +16384
    const int tid = threadIdx.x, warp = tid >> 5, lane = tid & 31;
    const int rowBase = blockIdx.y * 128, colBase = blockIdx.x * 128;
    const int wm = warp & 3, wn = warp >> 2;        // 4x2 warps -> 32x64 tiles
    const int gl = (lane >> 3) & 1, gh = lane >> 4, lr = lane & 7;

    auto load_stage = [&](int t, int buf){
        uint32_t aBuf = abase + buf * 32768;
        uint32_t bBuf = aBuf + 16384;
        int k0 = t * BK2;
        #pragma unroll
        for (int it = 0; it < 4; it++){
            int idx = tid + it * 256;       // 0..1023
            int r = idx >> 3, c = idx & 7;  // row, 16B chunk
            uint32_t off = (uint32_t)(r * 128 + ((c ^ (r & 7)) * 16));
            cp16(aBuf + off, &A[(size_t)(rowBase + r) * 512 + k0 + c * 8]);
            cp16(bBuf + off, &W[(size_t)(colBase + r) * 512 + k0 + c * 8]);
        }
        asm volatile("cp.async.commit_group;");
    };

    float acc[2][8][4] = {};

    load_stage(0, 0);
    load_stage(1, 1);

    for (int t = 0; t < 8; t++){
        if (t < 6) asm volatile("cp.async.wait_group 1;" ::: "memory");
        else       asm volatile("cp.async.wait_group 0;" ::: "memory");
        __syncthreads();
        uint32_t aBuf = abase + (t & 1) * 32768;
        uint32_t bBuf = aBuf + 16384;

        #pragma unroll
        for (int kk = 0; kk < 4; kk++){
            int kc = kk * 2 + gh;          // this lane's 16B k-chunk
            uint32_t a[2][4], b[4][4];
            #pragma unroll
            for (int mi = 0; mi < 2; mi++){
                int row = wm * 32 + mi * 16 + gl * 8 + lr;
                uint32_t addr = aBuf + (uint32_t)(row * 128 + ((kc ^ lr) * 16));
                ldsm4(a[mi][0], a[mi][1], a[mi][2], a[mi][3], addr);
            }
            #pragma unroll
            for (int nq = 0; nq < 4; nq++){
                int nrow = wn * 64 + nq * 16 + gl * 8 + lr;
                uint32_t addr = bBuf + (uint32_t)(nrow * 128 + ((kc ^ lr) * 16));
                ldsm4(b[nq][0], b[nq][1], b[nq][2], b[nq][3], addr);
            }
            #pragma unroll
            for (int mi = 0; mi < 2; mi++)
                #pragma unroll
                for (int nq = 0; nq < 4; nq++){
                    #pragma unroll
                    for (int hf = 0; hf < 2; hf++){
                        float* d = acc[mi][nq * 2 + hf];
                        asm volatile(
                            "mma.sync.aligned.m16n8k16.row.col.f32.f16.f16.f32 "
                            "{%0,%1,%2,%3}, {%4,%5,%6,%7}, {%8,%9}, {%0,%1,%2,%3};"
                            : "+f"(d[0]), "+f"(d[1]), "+f"(d[2]), "+f"(d[3])
                            : "r"(a[mi][0]), "r"(a[mi][1]), "r"(a[mi][2]), "r"(a[mi][3]),
                              "r"(b[nq][hf]), "r"(b[nq][2 + hf]));
                    }
                }
        }
        __syncthreads();
        if (t + 2 < 8) load_stage(t + 2, t & 1);
    }

    // ---- epilogue: fused bias + (1-gate)*sin, half store ----
    const int gg = lane >> 2, tt = lane & 3;
    #pragma unroll
    for (int mi = 0; mi < 2; mi++){
        int row0 = rowBase + wm * 32 + mi * 16 + gg;
        #pragma unroll
        for (int ni = 0; ni < 8; ni++){
            int col = colBase + wn * 64 + ni * 8 + tt * 2;
            float b0 = bias[col], b1 = bias[col + 1];
            #pragma unroll
            for (int h = 0; h < 2; h++){
                int row = row0 + h * 8;
                int strand = row / NV;
                float g0 = 1.f - gate[(size_t)strand * MH + col];
                float g1 = 1.f - gate[(size_t)strand * MH + col + 1];
                float v0 = g0 * __sinf(acc[mi][ni][h * 2 + 0] + b0);
                float v1 = g1 * __sinf(acc[mi][ni][h * 2 + 1] + b1);
                *reinterpret_cast<__half2*>(&out[(size_t)row * 512 + col]) =
                    __floats2half2_rn(v0, v1);
            }
        }
    }
}

// ================= decoder (reads half H) =================
__global__ void dec_kernel(const __half* __restrict__ H, const float* __restrict__ bd)
{
    __shared__ float wd[3 * SH];
    for (int i = threadIdx.x; i < 3 * SH; i += blockDim.x) wd[i] = g_wdec[i];
    __syncthreads();
    int warp = threadIdx.x >> 5, lane = threadIdx.x & 31;
    size_t row = (size_t)blockIdx.x * 8 + warp;
    const __half2* h2 = reinterpret_cast<const __half2*>(H + row * SH);
    float a0 = 0.f, a1 = 0.f, a2 = 0.f;
    for (int i = lane; i < SH / 2; i += 32) {
        float2 x = __half22float2(h2[i]);
        int j = i * 2;
        a0 = fmaf(x.x, wd[j],          a0); a0 = fmaf(x.y, wd[j + 1],          a0);
        a1 = fmaf(x.x, wd[SH + j],     a1); a1 = fmaf(x.y, wd[SH + j + 1],     a1);
        a2 = fmaf(x.x, wd[2*SH + j],   a2); a2 = fmaf(x.y, wd[2*SH + j + 1],   a2);
    }
    #pragma unroll
    for (int o = 16; o > 0; o >>= 1) {
        a0 += __shfl_down_sync(0xFFFFFFFFu, a0, o);
        a1 += __shfl_down_sync(0xFFFFFFFFu, a1, o);
        a2 += __shfl_down_sync(0xFFFFFFFFu, a2, o);
    }
    if (lane == 0) {
        g_dir[row * 3 + 0] = (a0 + bd[0]) * 0.01f;
        g_dir[row * 3 + 1] = (a1 + bd[1]) * 0.01f;
        g_dir[row * 3 + 2] = (a2 + bd[2]) * 0.01f;
    }
}

// ================= cumsum =================
__global__ void cumsum_kernel(float* __restrict__ out)
{
    int idx = blockIdx.x * blockDim.x + threadIdx.x;
    if (idx >= NS * 3) return;
    int s = idx / 3, d = idx - s * 3;
    float acc = 0.f;
    out[(size_t)s * 300 + d] = 0.f;
    for (int p = 0; p < NV; p++) {
        acc += g_dir[((size_t)s * NV + p) * 3 + d];
        out[(size_t)s * 300 + (size_t)(p + 1) * 3 + d] = acc;
    }
}

// ================= host launch =================
static void* sym(const void* s) { void* p = nullptr; cudaGetSymbolAddress(&p, s); return p; }

extern "C" void kernel_launch(void* const* d_in, const int* in_sizes, int n_in,
                              void* d_out, int out_size)
{
    const float* X   = (const float*)d_in[0];
    const float* mv0 = (const float*)d_in[1];  const float* mg0 = (const float*)d_in[2];  const float* mb0 = (const float*)d_in[3];
    const float* mv1 = (const float*)d_in[4];  const float* mg1 = (const float*)d_in[5];  const float* mb1 = (const float*)d_in[6];
    const float* mv2 = (const float*)d_in[7];  const float* mg2 = (const float*)d_in[8];  const float* mb2 = (const float*)d_in[9];
    const float* sv0 = (const float*)d_in[10]; const float* sg0 = (const float*)d_in[11]; const float* sb0 = (const float*)d_in[12];
    const float* sv1 = (const float*)d_in[13]; const float* sg1 = (const float*)d_in[14]; const float* sb1 = (const float*)d_in[15];
    const float* sv2 = (const float*)d_in[16]; const float* sg2 = (const float*)d_in[17]; const float* sb2 = (const float*)d_in[18];
    const float* dv  = (const float*)d_in[19]; const float* dg  = (const float*)d_in[20]; const float* db  = (const float*)d_in[21];
    float* out = (float*)d_out;

    float*  wmod0 = (float*)sym(g_wmod0);
    float*  wmod1 = (float*)sym(g_wmod1);
    float*  wmod2 = (float*)sym(g_wmod2);
    __half* hW1   = (__half*)sym(g_hW1);
    __half* hW2   = (__half*)sym(g_hW2);
    float*  M0    = (float*)sym(g_M0);
    float*  M1    = (float*)sym(g_M1);
    float*  M2    = (float*)sym(g_M2);
    float*  Z0    = (float*)sym(g_Z0);
    float*  Z1    = (float*)sym(g_Z1);
    float*  Xr    = (float*)sym(g_Xr);
    __half* hHA   = (__half*)sym(g_hHA);
    __half* hHB   = (__half*)sym(g_hHB);

    const int mod_smem = 2 * (BMM + BNM) * SST * 4;   // 73728
    const int tc_smem  = 65536 + 1024;                // 2 stages of 32KB + align slack
    static int attr_done = 0;
    if (!attr_done) {
        cudaFuncSetAttribute(gemm_mod_kernel, cudaFuncAttributeMaxDynamicSharedMemorySize, mod_smem);
        cudaFuncSetAttribute(tc_fp16_kernel,  cudaFuncAttributeMaxDynamicSharedMemorySize, tc_smem);
        attr_done = 1;
    }

    // launch 0: all prep fused
    prep_kernel<<<2726, 256>>>(mv0, mg0, mv1, mg1, mv2, mg2, sv1, sg1, sv2, sg2,
                               dv, dg, sv0, sg0, sb0, X);

    // launches 1-3: modulation chain
    {
        dim3 grid(512 / BNM, NS / BMM);
        gemm_mod_kernel<<<grid, 256, mod_smem>>>(Xr, wmod0, mb0, M0, Z0, INCH);
        gemm_mod_kernel<<<grid, 256, mod_smem>>>(Z0, wmod1, mb1, M1, Z1, KCAT);
        gemm_mod_kernel<<<grid, 256, mod_smem>>>(Z1, wmod2, mb2, M2, nullptr, KCAT);
    }

    // launch 4: H0 = (1-M0)*s0 -> half
    gate0_kernel<<<ROWS, SH>>>();

    // launches 5-6: two big fp16 tensor-core GEMMs
    {
        dim3 grid(512 / 128, ROWS / 128);
        tc_fp16_kernel<<<grid, 256, tc_smem>>>(hHA, hW1, sb1, M1, hHB);
        tc_fp16_kernel<<<grid, 256, tc_smem>>>(hHB, hW2, sb2, M2, hHA);
    }

    // launches 7-8: decoder + cumsum
    dec_kernel<<<ROWS / 8, 256>>>(hHA, db);
    cumsum_kernel<<<(NS * 3 + 255) / 256, 256>>>(out);
    (void)in_sizes; (void)n_in; (void)out_size;
}

// round 8
// speedup vs baseline: 5.6949x; 1.7506x over previous
#include <cuda_runtime.h>
#include <cuda_fp16.h>
#include <cstdint>

// ---------------- problem constants ----------------
#define NS      1024
#define NV      99
#define ROWS    (NS*NV)       // 101376
#define INCH    64
#define MH      512
#define SH      512
#define KCAT    (INCH+MH)     // 576
#define SCALE0  30.0f

// ---------------- device scratch ----------------
__device__ float  g_wmod0[MH*INCH];
__device__ float  g_wmod1[MH*KCAT];
__device__ float  g_wmod2[MH*KCAT];
__device__ __half g_hW1[SH*SH];
__device__ __half g_hW2[SH*SH];
__device__ float  g_wdec[3*SH];
__device__ float  g_s0[NV*SH];
__device__ float  g_M0[NS*MH];
__device__ float  g_M1[NS*MH];
__device__ float  g_M2[NS*MH];
__device__ float  g_Z0[NS*KCAT];
__device__ float  g_Z1[NS*KCAT];
__device__ float  g_Xr[NS*INCH];
__device__ __half g_hHB[(size_t)ROWS*SH];
__device__ float  g_dir[(size_t)ROWS*3];

__device__ __forceinline__ float rna_tf32(float x){
    float y; asm("cvt.rna.tf32.f32 %0, %1;" : "=f"(y) : "f"(x)); return y;
}
__device__ __forceinline__ void cp16(uint32_t s, const void* g){
    asm volatile("cp.async.cg.shared.global [%0], [%1], 16;" :: "r"(s), "l"(g));
}

// ================= prep: weight-norms + s0 + X rounding (one launch) ============
__global__ void prep_kernel(const float* __restrict__ mv0, const float* __restrict__ mg0,
                            const float* __restrict__ mv1, const float* __restrict__ mg1,
                            const float* __restrict__ mv2, const float* __restrict__ mg2,
                            const float* __restrict__ sv1, const float* __restrict__ sg1,
                            const float* __restrict__ sv2, const float* __restrict__ sg2,
                            const float* __restrict__ dv,  const float* __restrict__ dg,
                            const float* __restrict__ sv0, const float* __restrict__ sg0,
                            const float* __restrict__ sb0, const float* __restrict__ X)
{
    __shared__ float red[256];
    int b = blockIdx.x, tid = threadIdx.x;
    if (b < 2563) {
        const float* v; const float* g; int cols, r, mode; // 0=fp32,1=tf32,2=half
        float*  o32 = nullptr; __half* o16 = nullptr;
        if      (b < 512)  { v=mv0; g=mg0; o32=g_wmod0; cols=INCH; r=b;      mode=1; }
        else if (b < 1024) { v=mv1; g=mg1; o32=g_wmod1; cols=KCAT; r=b-512;  mode=1; }
        else if (b < 1536) { v=mv2; g=mg2; o32=g_wmod2; cols=KCAT; r=b-1024; mode=1; }
        else if (b < 2048) { v=sv1; g=sg1; o16=g_hW1;   cols=SH;   r=b-1536; mode=2; }
        else if (b < 2560) { v=sv2; g=sg2; o16=g_hW2;   cols=SH;   r=b-2048; mode=2; }
        else               { v=dv;  g=dg;  o32=g_wdec;  cols=SH;   r=b-2560; mode=0; }
        const float* vr = v + (size_t)r * cols;
        float ss = 0.f;
        for (int c = tid; c < cols; c += 256) { float x = vr[c]; ss += x * x; }
        red[tid] = ss; __syncthreads();
        for (int s = 128; s > 0; s >>= 1) {
            if (tid < s) red[tid] += red[tid + s];
            __syncthreads();
        }
        float scale = g[r] * rsqrtf(red[0]);
        for (int c = tid; c < cols; c += 256) {
            float w = vr[c] * scale;
            if (mode == 2)      o16[(size_t)r * cols + c] = __float2half(w);
            else if (mode == 1) o32[(size_t)r * cols + c] = rna_tf32(w);
            else                o32[(size_t)r * cols + c] = w;
        }
    } else if (b < 2662) {          // s0 table
        int p = b - 2563;
        float t = (float)p / 99.f;
        for (int j = tid; j < SH; j += 256) {
            float vv = sv0[j];
            float w  = sg0[j] * vv * rsqrtf(vv * vv);
            g_s0[p * SH + j] = sinf(SCALE0 * (t * w + sb0[j]));
        }
    } else {                        // X rounding + Z prefix
        int i0 = (b - 2662) * 256 + tid;
        for (int i = i0; i < NS * INCH; i += 64 * 256) {
            float v = rna_tf32(X[i]);
            int s = i >> 6, c = i & 63;
            g_Xr[i] = v;
            g_Z0[(size_t)s * KCAT + c] = v;
            g_Z1[(size_t)s * KCAT + c] = v;
        }
    }
}

// ================= mod GEMM (mma.sync tf32, silu, Z-writeback) — 64x128 tiles ====
#define BMM 64
#define BNM 128
#define BKM 32
#define SST 36
__global__ __launch_bounds__(256, 2)
void gemm_mod_kernel(const float* __restrict__ A, const float* __restrict__ W,
                     const float* __restrict__ bias, float* __restrict__ out,
                     float* __restrict__ zout, int K)
{
    extern __shared__ float sm[];
    float* sA = sm;                           // 2 * 64 * SST
    float* sB = sm + 2 * BMM * SST;           // 2 * 128 * SST
    const int tid = threadIdx.x;
    const int rowBase = blockIdx.y * BMM;
    const int colBase = blockIdx.x * BNM;
    const uint32_t sA_u = (uint32_t)__cvta_generic_to_shared(sA);
    const uint32_t sB_u = (uint32_t)__cvta_generic_to_shared(sB);
    const int lane = tid & 31, warp = tid >> 5;
    const int wm = warp & 3, wn = warp >> 2;   // warp tile 16 x 64
    const int gg = lane >> 2, tt = lane & 3;
    float acc[8][4] = {};
    const int nk = K / BKM;

    auto load_stage = [&](int i, int buf){
        int k0 = i * BKM;
        #pragma unroll
        for (int it = 0; it < 2; it++){
            int c  = tid + it * 256;      // 0..511
            int r  = c >> 3;
            int kc = (c & 7) * 4;
            cp16(sA_u + (uint32_t)((buf * BMM * SST + r * SST + kc) * 4),
                 &A[(size_t)(rowBase + r) * K + k0 + kc]);
        }
        #pragma unroll
        for (int it = 0; it < 4; it++){
            int c  = tid + it * 256;      // 0..1023
            int r  = c >> 3;
            int kc = (c & 7) * 4;
            cp16(sB_u + (uint32_t)((buf * BNM * SST + r * SST + kc) * 4),
                 &W[(size_t)(colBase + r) * K + k0 + kc]);
        }
        asm volatile("cp.async.commit_group;");
    };

    load_stage(0, 0);
    for (int i = 0; i < nk; i++){
        if (i + 1 < nk) { load_stage(i + 1, (i + 1) & 1); asm volatile("cp.async.wait_group 1;"); }
        else            { asm volatile("cp.async.wait_group 0;"); }
        __syncthreads();
        const float* cA = sA + (i & 1) * BMM * SST;
        const float* cB = sB + (i & 1) * BNM * SST;
        #pragma unroll
        for (int kk = 0; kk < BKM; kk += 8){
            uint32_t a[4], b[8][2];
            {
                int r = wm * 16 + gg;
                a[0] = __float_as_uint(cA[r * SST + kk + tt]);
                a[1] = __float_as_uint(cA[(r + 8) * SST + kk + tt]);
                a[2] = __float_as_uint(cA[r * SST + kk + tt + 4]);
                a[3] = __float_as_uint(cA[(r + 8) * SST + kk + tt + 4]);
            }
            #pragma unroll
            for (int ni = 0; ni < 8; ni++){
                int c = wn * 64 + ni * 8 + gg;
                b[ni][0] = __float_as_uint(cB[c * SST + kk + tt]);
                b[ni][1] = __float_as_uint(cB[c * SST + kk + tt + 4]);
            }
            #pragma unroll
            for (int ni = 0; ni < 8; ni++){
                float* d = acc[ni];
                asm volatile(
                    "mma.sync.aligned.m16n8k8.row.col.f32.tf32.tf32.f32 "
                    "{%0,%1,%2,%3}, {%4,%5,%6,%7}, {%8,%9}, {%0,%1,%2,%3};"
                    : "+f"(d[0]), "+f"(d[1]), "+f"(d[2]), "+f"(d[3])
                    : "r"(a[0]), "r"(a[1]), "r"(a[2]), "r"(a[3]),
                      "r"(b[ni][0]), "r"(b[ni][1]));
            }
        }
        __syncthreads();
    }

    int row0 = rowBase + wm * 16 + gg;
    #pragma unroll
    for (int ni = 0; ni < 8; ni++){
        int col = colBase + wn * 64 + ni * 8 + tt * 2;
        float b0 = bias[col], b1 = bias[col + 1];
        #pragma unroll
        for (int h = 0; h < 2; h++){
            int row = row0 + h * 8;
            float v0 = acc[ni][h * 2 + 0] + b0;
            float v1 = acc[ni][h * 2 + 1] + b1;
            v0 = v0 / (1.f + __expf(-v0));
            v1 = v1 / (1.f + __expf(-v1));
            *reinterpret_cast<float2*>(&out[(size_t)row * 512 + col]) = make_float2(v0, v1);
            if (zout)
                *reinterpret_cast<float2*>(&zout[(size_t)row * KCAT + 64 + col]) =
                    make_float2(rna_tf32(v0), rna_tf32(v1));
        }
    }
}

// ================= fp16 tensor-core GEMM (101376 x 512 x 512) ====================
// MODE 1: A computed on the fly = half((1-gateA[strand,k])*s0[p,k]); epilogue stores
//         half out = (1-gateE)*sin(acc+bias).
// MODE 2: A loaded from half; epilogue feeds fused decoder (atomicAdd into g_dir),
//         no store.
#define BK2 64
__device__ __forceinline__ void ldsm4(uint32_t& r0, uint32_t& r1, uint32_t& r2, uint32_t& r3,
                                      uint32_t addr){
    asm volatile("ldmatrix.sync.aligned.m8n8.x4.shared.b16 {%0,%1,%2,%3}, [%4];"
                 : "=r"(r0), "=r"(r1), "=r"(r2), "=r"(r3) : "r"(addr));
}

template<int MODE>
__global__ __launch_bounds__(256, 2)
void tc_fp16_kernel(const __half* __restrict__ A, const __half* __restrict__ W,
                    const float* __restrict__ bias, const float* __restrict__ gateE,
                    const float* __restrict__ gateA, __half* __restrict__ out)
{
    extern __shared__ __align__(1024) char smem_raw[];
    uint32_t base  = (uint32_t)__cvta_generic_to_shared(smem_raw);
    uint32_t abase = (base + 1023u) & ~1023u;
    const int tid = threadIdx.x, warp = tid >> 5, lane = tid & 31;
    const int rowBase = blockIdx.y * 128, colBase = blockIdx.x * 128;
    const int wm = warp & 3, wn = warp >> 2;
    const int gl = (lane >> 3) & 1, gh = lane >> 4, lr = lane & 7;

    // decoder weight slice (MODE 2)
    float* wds = reinterpret_cast<float*>(smem_raw + (abase - base) + 65536);
    if (MODE == 2 && tid < 128) {
        #pragma unroll
        for (int d = 0; d < 3; d++)
            wds[d * 128 + tid] = g_wdec[d * 512 + colBase + tid];
    }

    auto load_B = [&](int t, int buf){
        uint32_t bBuf = abase + buf * 32768 + 16384;
        int k0 = t * BK2;
        #pragma unroll
        for (int it = 0; it < 4; it++){
            int idx = tid + it * 256;
            int r = idx >> 3, c = idx & 7;
            uint32_t off = (uint32_t)(r * 128 + ((c ^ (r & 7)) * 16));
            cp16(bBuf + off, &W[(size_t)(colBase + r) * 512 + k0 + c * 8]);
        }
    };
    auto load_A = [&](int t, int buf){
        uint32_t aBuf = abase + buf * 32768;
        int k0 = t * BK2;
        #pragma unroll
        for (int it = 0; it < 4; it++){
            int idx = tid + it * 256;
            int r = idx >> 3, c = idx & 7;
            uint32_t off = (uint32_t)(r * 128 + ((c ^ (r & 7)) * 16));
            cp16(aBuf + off, &A[(size_t)(rowBase + r) * 512 + k0 + c * 8]);
        }
    };
    auto produce_A = [&](int t, int buf){           // MODE 1: (1-M0)*s0 -> half smem
        uint32_t aBuf = abase + buf * 32768;
        int k0 = t * BK2;
        #pragma unroll
        for (int it = 0; it < 4; it++){
            int idx = tid + it * 256;
            int r = idx >> 3, c = idx & 7;
            int row = rowBase + r;
            int strand = row / NV, p = row - strand * NV;
            const float4* m4 = reinterpret_cast<const float4*>(&gateA[(size_t)strand * MH + k0 + c * 8]);
            const float4* s4 = reinterpret_cast<const float4*>(&g_s0[p * SH + k0 + c * 8]);
            float4 m0 = m4[0], m1 = m4[1], s0v = s4[0], s1v = s4[1];
            __half2 h0 = __floats2half2_rn((1.f - m0.x) * s0v.x, (1.f - m0.y) * s0v.y);
            __half2 h1 = __floats2half2_rn((1.f - m0.z) * s0v.z, (1.f - m0.w) * s0v.w);
            __half2 h2 = __floats2half2_rn((1.f - m1.x) * s1v.x, (1.f - m1.y) * s1v.y);
            __half2 h3 = __floats2half2_rn((1.f - m1.z) * s1v.z, (1.f - m1.w) * s1v.w);
            uint32_t off = (uint32_t)(r * 128 + ((c ^ (r & 7)) * 16));
            asm volatile("st.shared.v4.b32 [%0], {%1,%2,%3,%4};"
                         :: "r"(aBuf + off),
                            "r"(*reinterpret_cast<uint32_t*>(&h0)),
                            "r"(*reinterpret_cast<uint32_t*>(&h1)),
                            "r"(*reinterpret_cast<uint32_t*>(&h2)),
                            "r"(*reinterpret_cast<uint32_t*>(&h3)) : "memory");
        }
    };
    auto load_stage = [&](int t, int buf){
        if (MODE == 1) produce_A(t, buf); else load_A(t, buf);
        load_B(t, buf);
        asm volatile("cp.async.commit_group;");
    };

    float acc[2][8][4] = {};

    load_stage(0, 0);
    load_stage(1, 1);

    for (int t = 0; t < 8; t++){
        if (t < 6) asm volatile("cp.async.wait_group 1;" ::: "memory");
        else       asm volatile("cp.async.wait_group 0;" ::: "memory");
        __syncthreads();
        uint32_t aBuf = abase + (t & 1) * 32768;
        uint32_t bBuf = aBuf + 16384;

        #pragma unroll
        for (int kk = 0; kk < 4; kk++){
            int kc = kk * 2 + gh;
            uint32_t a[2][4], b[4][4];
            #pragma unroll
            for (int mi = 0; mi < 2; mi++){
                int row = wm * 32 + mi * 16 + gl * 8 + lr;
                uint32_t addr = aBuf + (uint32_t)(row * 128 + ((kc ^ lr) * 16));
                ldsm4(a[mi][0], a[mi][1], a[mi][2], a[mi][3], addr);
            }
            #pragma unroll
            for (int nq = 0; nq < 4; nq++){
                int nrow = wn * 64 + nq * 16 + gl * 8 + lr;
                uint32_t addr = bBuf + (uint32_t)(nrow * 128 + ((kc ^ lr) * 16));
                ldsm4(b[nq][0], b[nq][1], b[nq][2], b[nq][3], addr);
            }
            #pragma unroll
            for (int mi = 0; mi < 2; mi++)
                #pragma unroll
                for (int nq = 0; nq < 4; nq++){
                    #pragma unroll
                    for (int hf = 0; hf < 2; hf++){
                        float* d = acc[mi][nq * 2 + hf];
                        asm volatile(
                            "mma.sync.aligned.m16n8k16.row.col.f32.f16.f16.f32 "
                            "{%0,%1,%2,%3}, {%4,%5,%6,%7}, {%8,%9}, {%0,%1,%2,%3};"
                            : "+f"(d[0]), "+f"(d[1]), "+f"(d[2]), "+f"(d[3])
                            : "r"(a[mi][0]), "r"(a[mi][1]), "r"(a[mi][2]), "r"(a[mi][3]),
                              "r"(b[nq][hf]), "r"(b[nq][2 + hf]));
                    }
                }
        }
        __syncthreads();
        if (t + 2 < 8) load_stage(t + 2, t & 1);
    }

    // ---- epilogue ----
    const int gg = lane >> 2, tt = lane & 3;
    float p3[4][3];
    if (MODE == 2){
        #pragma unroll
        for (int q = 0; q < 4; q++){ p3[q][0] = 0.f; p3[q][1] = 0.f; p3[q][2] = 0.f; }
    }
    #pragma unroll
    for (int mi = 0; mi < 2; mi++){
        int row0 = rowBase + wm * 32 + mi * 16 + gg;
        #pragma unroll
        for (int ni = 0; ni < 8; ni++){
            int col = colBase + wn * 64 + ni * 8 + tt * 2;
            float b0 = bias[col], b1 = bias[col + 1];
            #pragma unroll
            for (int h = 0; h < 2; h++){
                int row = row0 + h * 8;
                int strand = row / NV;
                float g0 = 1.f - gateE[(size_t)strand * MH + col];
                float g1 = 1.f - gateE[(size_t)strand * MH + col + 1];
                float v0 = g0 * __sinf(acc[mi][ni][h * 2 + 0] + b0);
                float v1 = g1 * __sinf(acc[mi][ni][h * 2 + 1] + b1);
                if (MODE == 1){
                    *reinterpret_cast<__half2*>(&out[(size_t)row * 512 + col]) =
                        __floats2half2_rn(v0, v1);
                } else {
                    int lc = col - colBase;
                    int q = mi * 2 + h;
                    #pragma unroll
                    for (int d = 0; d < 3; d++)
                        p3[q][d] += v0 * wds[d * 128 + lc] + v1 * wds[d * 128 + lc + 1];
                }
            }
        }
    }
    if (MODE == 2){
        // reduce over tt lanes (quad), then atomicAdd
        #pragma unroll
        for (int q = 0; q < 4; q++)
            #pragma unroll
            for (int d = 0; d < 3; d++){
                float v = p3[q][d];
                v += __shfl_xor_sync(0xFFFFFFFFu, v, 1);
                v += __shfl_xor_sync(0xFFFFFFFFu, v, 2);
                p3[q][d] = v;
            }
        if (tt == 0){
            int rb = rowBase + wm * 32 + gg;
            #pragma unroll
            for (int q = 0; q < 4; q++){
                int row = rb + (q & 1) * 8 + (q >> 1) * 16;
                #pragma unroll
                for (int d = 0; d < 3; d++)
                    atomicAdd(&g_dir[(size_t)row * 3 + d], p3[q][d] * 0.01f);
            }
        }
    }
}

// ================= cumsum (adds decoder bias per step) =================
__global__ void cumsum_kernel(float* __restrict__ out, const float* __restrict__ bd)
{
    int idx = blockIdx.x * blockDim.x + threadIdx.x;
    if (idx >= NS * 3) return;
    int s = idx / 3, d = idx - s * 3;
    float bias = bd[d] * 0.01f;
    float acc = 0.f;
    out[(size_t)s * 300 + d] = 0.f;
    for (int p = 0; p < NV; p++) {
        acc += g_dir[((size_t)s * NV + p) * 3 + d] + bias;
        out[(size_t)s * 300 + (size_t)(p + 1) * 3 + d] = acc;
    }
}

// ================= host launch =================
static void* sym(const void* s) { void* p = nullptr; cudaGetSymbolAddress(&p, s); return p; }

extern "C" void kernel_launch(void* const* d_in, const int* in_sizes, int n_in,
                              void* d_out, int out_size)
{
    const float* X   = (const float*)d_in[0];
    const float* mv0 = (const float*)d_in[1];  const float* mg0 = (const float*)d_in[2];  const float* mb0 = (const float*)d_in[3];
    const float* mv1 = (const float*)d_in[4];  const float* mg1 = (const float*)d_in[5];  const float* mb1 = (const float*)d_in[6];
    const float* mv2 = (const float*)d_in[7];  const float* mg2 = (const float*)d_in[8];  const float* mb2 = (const float*)d_in[9];
    const float* sv0 = (const float*)d_in[10]; const float* sg0 = (const float*)d_in[11]; const float* sb0 = (const float*)d_in[12];
    const float* sv1 = (const float*)d_in[13]; const float* sg1 = (const float*)d_in[14]; const float* sb1 = (const float*)d_in[15];
    const float* sv2 = (const float*)d_in[16]; const float* sg2 = (const float*)d_in[17]; const float* sb2 = (const float*)d_in[18];
    const float* dv  = (const float*)d_in[19]; const float* dg  = (const float*)d_in[20]; const float* db  = (const float*)d_in[21];
    float* out = (float*)d_out;

    float*  wmod0 = (float*)sym(g_wmod0);
    float*  wmod1 = (float*)sym(g_wmod1);
    float*  wmod2 = (float*)sym(g_wmod2);
    __half* hW1   = (__half*)sym(g_hW1);
    __half* hW2   = (__half*)sym(g_hW2);
    float*  M0    = (float*)sym(g_M0);
    float*  M1    = (float*)sym(g_M1);
    float*  M2    = (float*)sym(g_M2);
    float*  Z0    = (float*)sym(g_Z0);
    float*  Z1    = (float*)sym(g_Z1);
    float*  Xr    = (float*)sym(g_Xr);
    __half* hHB   = (__half*)sym(g_hHB);
    float*  dir   = (float*)sym(g_dir);

    const int mod_smem = 2 * (BMM + BNM) * SST * 4;   // 55296
    const int tc_smem  = 65536 + 1024 + 2048;         // stages + align + wdec slice
    static int attr_done = 0;
    if (!attr_done) {
        cudaFuncSetAttribute(gemm_mod_kernel, cudaFuncAttributeMaxDynamicSharedMemorySize, mod_smem);
        cudaFuncSetAttribute(tc_fp16_kernel<1>, cudaFuncAttributeMaxDynamicSharedMemorySize, tc_smem);
        cudaFuncSetAttribute(tc_fp16_kernel<2>, cudaFuncAttributeMaxDynamicSharedMemorySize, tc_smem);
        attr_done = 1;
    }

    // prep (launch 0)
    prep_kernel<<<2726, 256>>>(mv0, mg0, mv1, mg1, mv2, mg2, sv1, sg1, sv2, sg2,
                               dv, dg, sv0, sg0, sb0, X);

    // modulation chain (launches 1-3)
    {
        dim3 grid(512 / BNM, NS / BMM);
        gemm_mod_kernel<<<grid, 256, mod_smem>>>(Xr, wmod0, mb0, M0, Z0, INCH);
        gemm_mod_kernel<<<grid, 256, mod_smem>>>(Z0, wmod1, mb1, M1, Z1, KCAT);
        gemm_mod_kernel<<<grid, 256, mod_smem>>>(Z1, wmod2, mb2, M2, nullptr, KCAT);
    }

    // zero decoder accumulator (memset node, not a kernel launch)
    cudaMemsetAsync(dir, 0, (size_t)ROWS * 3 * sizeof(float), 0);

    // big GEMMs (launches 4-5): GEMM1 fuses gate0 on input; GEMM2 fuses decoder
    {
        dim3 grid(512 / 128, ROWS / 128);
        tc_fp16_kernel<1><<<grid, 256, tc_smem>>>(nullptr, hW1, sb1, M1, M0, hHB);
        tc_fp16_kernel<2><<<grid, 256, tc_smem>>>(hHB, hW2, sb2, M2, nullptr, nullptr);
    }

    // cumsum (launch 6)
    cumsum_kernel<<<(NS * 3 + 255) / 256, 256>>>(out, db);
    (void)in_sizes; (void)n_in; (void)out_size;
}